// round 14
// baseline (speedup 1.0000x reference)
#include <cuda_runtime.h>
#include <cuda_fp16.h>
#include <math.h>
#include <stdint.h>

#define EE 64
#define SSZ 128
#define FF 640
#define HH 256
#define GG 768          // 3*H
#define LLN 20
#define CC 32
#define BB (EE*SSZ)     // 8192
#define BLM (BB*LLN)    // 163840
#define EPSV 1e-5f

// ---------------- scratch (static __device__, no allocation) ----------------
__device__ __half g_xh [BB*FF];
__device__ __half g_x16[BB*HH];
__device__ __half g_gi16[BB*GG];
__device__ __half g_hs16[BLM*HH];   // BN2+PReLU applied
__device__ __half g_y216[BLM*HH];
__device__ __half g_wlin16[HH*FF];
__device__ __half g_wih16[GG*HH];
__device__ __half g_whh16[GG*HH];
__device__ __half g_wc16[HH*HH];
__device__ __half g_wmu16[CC*HH];
__device__ float g_s1[HH], g_o1[HH];
__device__ float g_s2[HH], g_o2[HH];
__device__ float g_s3[HH], g_o3[HH];
__device__ float g_al[3];

// ---------------- helpers ----------------------------------------------------
__device__ __forceinline__ uint32_t cvta_s(const void* p) {
    return (uint32_t)__cvta_generic_to_shared(p);
}
__device__ __forceinline__ void mma16(float* c, const uint32_t* a, const uint32_t* b) {
    asm volatile("mma.sync.aligned.m16n8k16.row.col.f32.f16.f16.f32 "
        "{%0,%1,%2,%3},{%4,%5,%6,%7},{%8,%9},{%0,%1,%2,%3};"
        : "+f"(c[0]), "+f"(c[1]), "+f"(c[2]), "+f"(c[3])
        : "r"(a[0]), "r"(a[1]), "r"(a[2]), "r"(a[3]), "r"(b[0]), "r"(b[1]));
}
#define LDSM4(r0,r1,r2,r3,addr) \
    asm volatile("ldmatrix.sync.aligned.m8n8.x4.shared.b16 {%0,%1,%2,%3}, [%4];" \
        : "=r"(r0),"=r"(r1),"=r"(r2),"=r"(r3) : "r"(addr))

__device__ __forceinline__ float sigf(float x) { return 1.f / (1.f + expf(-x)); }
__device__ __forceinline__ float2 h2f(uint32_t u) { return __half22float2(*(__half2*)&u); }
__device__ __forceinline__ uint32_t f2h(float a, float b) {
    __half2 h = __floats2half2_rn(a, b); return *(uint32_t*)&h;
}

// ---------------- prep ------------------------------------------------------
__global__ void prep_kernel(const float* g1,const float* b1,const float* m1,const float* v1,const float* a1,
                            const float* g2,const float* b2,const float* m2,const float* v2,const float* a2,
                            const float* g3,const float* b3,const float* m3,const float* v3,const float* a3)
{
    int i = threadIdx.x;
    float s;
    s = g1[i] / sqrtf(v1[i] + EPSV); g_s1[i] = s; g_o1[i] = b1[i] - m1[i]*s;
    s = g2[i] / sqrtf(v2[i] + EPSV); g_s2[i] = s; g_o2[i] = b2[i] - m2[i]*s;
    s = g3[i] / sqrtf(v3[i] + EPSV); g_s3[i] = s; g_o3[i] = b3[i] - m3[i]*s;
    if (i == 0) { g_al[0] = a1[0]; g_al[1] = a2[0]; g_al[2] = a3[0]; }
}

__global__ void cvt_kernel(const float* __restrict__ s, __half* __restrict__ d, int n8)
{
    int i = blockIdx.x * blockDim.x + threadIdx.x;
    if (i >= n8) return;
    float4 v0 = *(const float4*)(s + i*8);
    float4 v1 = *(const float4*)(s + i*8 + 4);
    *(uint4*)(d + i*8) = make_uint4(f2h(v0.x,v0.y), f2h(v0.z,v0.w), f2h(v1.x,v1.y), f2h(v1.z,v1.w));
}

#define CW0 (HH*FF/8)
#define CW1 (CW0 + GG*HH/8)
#define CW2 (CW1 + GG*HH/8)
#define CW3 (CW2 + HH*HH/8)
#define CW4 (CW3 + CC*HH/8)
__global__ void cvt_w_kernel(const float* wlin, const float* wih, const float* whh,
                             const float* wc, const float* wmu)
{
    int i = blockIdx.x * blockDim.x + threadIdx.x;
    if (i >= CW4) return;
    const float* s; __half* d; int j;
    if (i < CW0)      { s = wlin; d = g_wlin16; j = i; }
    else if (i < CW1) { s = wih;  d = g_wih16;  j = i - CW0; }
    else if (i < CW2) { s = whh;  d = g_whh16;  j = i - CW1; }
    else if (i < CW3) { s = wc;   d = g_wc16;   j = i - CW2; }
    else              { s = wmu;  d = g_wmu16;  j = i - CW3; }
    float4 v0 = *(const float4*)(s + (size_t)j*8);
    float4 v1 = *(const float4*)(s + (size_t)j*8 + 4);
    *(uint4*)(d + (size_t)j*8) = make_uint4(f2h(v0.x,v0.y), f2h(v0.z,v0.w), f2h(v1.x,v1.y), f2h(v1.z,v1.w));
}

// ---------------- fp16 GEMM (R12 pipeline, unchanged) ------------------------
template<int BM,int BN,int WM,int WN,int MODE,bool OUTH>
__global__ __launch_bounds__(256, 2) void hgemm3(
    const __half* __restrict__ A, const __half* __restrict__ W,
    const float* __restrict__ bias, void* __restrict__ Cst,
    int M, int N, int K)
{
    constexpr int PIT = 40;
    __shared__ __align__(16) __half Ah[2][BM*PIT];
    __shared__ __align__(16) __half Wh[2][BN*PIT];

    const int tid  = threadIdx.x;
    const int wid  = tid >> 5;
    const int lane = tid & 31;
    const int wm   = wid % WM;
    const int wn   = wid / WM;
    constexpr int WTM = BM / WM;
    constexpr int WTN = BN / WN;
    constexpr int MT  = WTM / 16;
    constexpr int NT  = WTN / 8;
    const int qr = lane >> 2, qc = lane & 3;
    const int l8 = lane & 7;

    const int m0 = blockIdx.y * BM;
    const int n0 = blockIdx.x * BN;

    constexpr int ACH = BM * 4;
    constexpr int WCH = BN * 4;
    constexpr int AIT = ACH / 256;
    constexpr int WIT = (WCH + 255) / 256;

    const int r = tid >> 2, c = tid & 3;

    float acc[MT][NT][4];
#pragma unroll
    for (int i = 0; i < MT; i++)
#pragma unroll
        for (int j = 0; j < NT; j++)
#pragma unroll
            for (int q = 0; q < 4; q++) acc[i][j][q] = 0.f;

    const int T = K / 32;

    {
#pragma unroll
        for (int it = 0; it < AIT; it++) {
            int rr = r + it*64;
            *(uint4*)&Ah[0][rr*PIT + c*8] = *(const uint4*)(A + (size_t)(m0 + rr) * K + c*8);
        }
#pragma unroll
        for (int it = 0; it < WIT; it++) {
            int idx = tid + it*256;
            if ((WCH % 256 == 0) || idx < WCH) {
                int rr = idx >> 2, cc = idx & 3;
                *(uint4*)&Wh[0][rr*PIT + cc*8] = *(const uint4*)(W + (size_t)(n0 + rr) * K + cc*8);
            }
        }
    }
    __syncthreads();

    int buf = 0;
    for (int t = 0; t < T; t++) {
        uint4 aP[AIT], wP[WIT];
        if (t + 1 < T) {
#pragma unroll
            for (int it = 0; it < AIT; it++) {
                int rr = r + it*64;
                aP[it] = *(const uint4*)(A + (size_t)(m0 + rr) * K + (t+1)*32 + c*8);
            }
#pragma unroll
            for (int it = 0; it < WIT; it++) {
                int idx = tid + it*256;
                if ((WCH % 256 == 0) || idx < WCH) {
                    int rr = idx >> 2, cc = idx & 3;
                    wP[it] = *(const uint4*)(W + (size_t)(n0 + rr) * K + (t+1)*32 + cc*8);
                }
            }
        }

#pragma unroll
        for (int ks = 0; ks < 2; ks++) {
            uint32_t af[MT][4], bf[NT][2];
#pragma unroll
            for (int mt = 0; mt < MT; mt++) {
                const int m  = wm*WTM + mt*16 + l8 + ((lane >> 3) & 1) * 8;
                const int ck = 2*ks + (lane >> 4);
                uint32_t ad = cvta_s(&Ah[buf][m*PIT + ck*8]);
                LDSM4(af[mt][0], af[mt][1], af[mt][2], af[mt][3], ad);
            }
#pragma unroll
            for (int np = 0; np < NT/2; np++) {
                const int n  = wn*WTN + np*16 + l8 + ((lane >> 4) & 1) * 8;
                const int ck = 2*ks + ((lane >> 3) & 1);
                uint32_t bd = cvta_s(&Wh[buf][n*PIT + ck*8]);
                LDSM4(bf[2*np][0], bf[2*np][1], bf[2*np+1][0], bf[2*np+1][1], bd);
            }
#pragma unroll
            for (int mt = 0; mt < MT; mt++)
#pragma unroll
                for (int nt = 0; nt < NT; nt++)
                    mma16(acc[mt][nt], af[mt], bf[nt]);
        }

        if (t + 1 < T) {
            const int nb = buf ^ 1;
#pragma unroll
            for (int it = 0; it < AIT; it++) {
                int rr = r + it*64;
                *(uint4*)&Ah[nb][rr*PIT + c*8] = aP[it];
            }
#pragma unroll
            for (int it = 0; it < WIT; it++) {
                int idx = tid + it*256;
                if ((WCH % 256 == 0) || idx < WCH) {
                    int rr = idx >> 2, cc = idx & 3;
                    *(uint4*)&Wh[nb][rr*PIT + cc*8] = wP[it];
                }
            }
            __syncthreads();
            buf = nb;
        }
    }

#pragma unroll
    for (int mt = 0; mt < MT; mt++) {
#pragma unroll
        for (int nt = 0; nt < NT; nt++) {
            const int row = m0 + wm*WTM + mt*16 + qr;
            const int col = n0 + wn*WTN + nt*8 + 2*qc;
            float2 bv = *(const float2*)(bias + col);
            float x0 = acc[mt][nt][0] + bv.x;
            float x1 = acc[mt][nt][1] + bv.y;
            float x2 = acc[mt][nt][2] + bv.x;
            float x3 = acc[mt][nt][3] + bv.y;
            if (MODE == 1 || MODE == 3) {
                const float* sp = (MODE == 1) ? g_s1 : g_s3;
                const float* op = (MODE == 1) ? g_o1 : g_o3;
                const float al  = (MODE == 1) ? g_al[0] : g_al[2];
                float2 sv = *(const float2*)(sp + col);
                float2 ov = *(const float2*)(op + col);
                x0 = fmaf(x0, sv.x, ov.x); x0 = x0>=0.f ? x0 : al*x0;
                x1 = fmaf(x1, sv.y, ov.y); x1 = x1>=0.f ? x1 : al*x1;
                x2 = fmaf(x2, sv.x, ov.x); x2 = x2>=0.f ? x2 : al*x2;
                x3 = fmaf(x3, sv.y, ov.y); x3 = x3>=0.f ? x3 : al*x3;
            }
            if (OUTH) {
                __half* C = (__half*)Cst;
                *(uint32_t*)&C[(size_t)row * N + col]       = f2h(x0, x1);
                *(uint32_t*)&C[(size_t)(row + 8) * N + col] = f2h(x2, x3);
            } else {
                float* C = (float*)Cst;
                *(float2*)&C[(size_t)row * N + col]       = make_float2(x0, x1);
                *(float2*)&C[(size_t)(row + 8) * N + col] = make_float2(x2, x3);
            }
        }
    }
}

// ---------------- persistent GRU: all 20 steps in one kernel -----------------
// CTA owns 64 batch rows. h (64x256) and gi (64x768) resident in smem for the
// whole kernel; only W_hh (L2) streams in and hs streams out. Per step:
// 2 N-chunks x 3 gates of 64x128x256 sub-GEMMs (R12 inner loop). r,z packed
// in regs across gate passes; h_new held in regs until post-sync commit.
#define PH 264                       // h row pitch (halfs)
#define PG 776                       // gi row pitch (halfs)
#define PW 40                        // W row pitch
#define GRUP_SMEM ((64*PH + 64*PG + 2*128*PW) * 2)   // 153600 B

__global__ __launch_bounds__(256, 1) void gru_persist(const float* __restrict__ bhh)
{
    extern __shared__ __half sm16[];
    __half* Hs = sm16;                         // [64][PH]
    __half* Gs = sm16 + 64*PH;                 // [64][PG]
    __half* Ws = sm16 + 64*PH + 64*PG;         // [2][128][PW]

    const int tid  = threadIdx.x;
    const int wid  = tid >> 5;
    const int lane = tid & 31;
    const int wm   = wid & 1;                  // 2 warps along M (WTM=32, MT=2)
    const int wn   = wid >> 1;                 // 4 warps along N (WTN=32, NT=4)
    const int qr = lane >> 2, qc = lane & 3;
    const int l8 = lane & 7;
    const int m0 = blockIdx.x * 64;

    // zero h
    for (int i = tid; i < 64*PH/8; i += 256)
        *(uint4*)&Hs[i*8] = make_uint4(0,0,0,0);
    // load gi tile (64 x 768)
    for (int i = tid; i < 64*96; i += 256) {
        int r = i / 96, c = i % 96;
        *(uint4*)&Gs[r*PG + c*8] = *(const uint4*)(g_gi16 + (size_t)(m0 + r) * GG + c*8);
    }
    __syncthreads();

    const float aA = g_al[1];

    for (int l = 0; l < LLN; l++) {
        uint32_t hnew[2][2][4][2];
#pragma unroll
        for (int nc = 0; nc < 2; nc++) {
            const int n0c = nc * 128;
            uint32_t rv[2][4][2], zv[2][4][2];
#pragma unroll
            for (int g = 0; g < 3; g++) {
                const __half* Wg = g_whh16 + (size_t)(g*HH + n0c) * HH;
                float acc[2][4][4];
#pragma unroll
                for (int i = 0; i < 2; i++)
#pragma unroll
                    for (int j = 0; j < 4; j++)
#pragma unroll
                        for (int q = 0; q < 4; q++) acc[i][j][q] = 0.f;

                __syncthreads();    // Ws reuse safe; orders h commit on first pass
#pragma unroll
                for (int it = 0; it < 2; it++) {
                    int idx = tid + it*256;
                    int r = idx >> 2, c = idx & 3;
                    *(uint4*)&Ws[r*PW + c*8] = *(const uint4*)(Wg + (size_t)r * HH + c*8);
                }
                __syncthreads();

                int buf = 0;
                for (int t = 0; t < 8; t++) {   // K=256, BK=32
                    uint4 wP[2];
                    if (t < 7) {
#pragma unroll
                        for (int it = 0; it < 2; it++) {
                            int idx = tid + it*256;
                            int r = idx >> 2, c = idx & 3;
                            wP[it] = *(const uint4*)(Wg + (size_t)r * HH + (t+1)*32 + c*8);
                        }
                    }
#pragma unroll
                    for (int ks = 0; ks < 2; ks++) {
                        uint32_t af[2][4], bf[4][2];
#pragma unroll
                        for (int mt = 0; mt < 2; mt++) {
                            const int m  = wm*32 + mt*16 + l8 + ((lane >> 3) & 1) * 8;
                            const int ck = t*4 + 2*ks + (lane >> 4);
                            uint32_t ad = cvta_s(&Hs[m*PH + ck*8]);
                            LDSM4(af[mt][0], af[mt][1], af[mt][2], af[mt][3], ad);
                        }
#pragma unroll
                        for (int np = 0; np < 2; np++) {
                            const int n  = wn*32 + np*16 + l8 + ((lane >> 4) & 1) * 8;
                            const int ck = 2*ks + ((lane >> 3) & 1);
                            uint32_t bd = cvta_s(&Ws[buf*128*PW + n*PW + ck*8]);
                            LDSM4(bf[2*np][0], bf[2*np][1], bf[2*np+1][0], bf[2*np+1][1], bd);
                        }
#pragma unroll
                        for (int mt = 0; mt < 2; mt++)
#pragma unroll
                            for (int nt = 0; nt < 4; nt++)
                                mma16(acc[mt][nt], af[mt], bf[nt]);
                    }
                    if (t < 7) {
                        const int nb = buf ^ 1;
#pragma unroll
                        for (int it = 0; it < 2; it++) {
                            int idx = tid + it*256;
                            int r = idx >> 2, c = idx & 3;
                            *(uint4*)&Ws[nb*128*PW + r*PW + c*8] = wP[it];
                        }
                        __syncthreads();
                        buf = nb;
                    }
                }

                // ---- gate epilogue ----
#pragma unroll
                for (int nt = 0; nt < 4; nt++) {
                    const int coll = wn*32 + nt*8 + 2*qc;
                    const int colg = n0c + coll;
                    float2 bb = *(const float2*)(bhh + g*HH + colg);
#pragma unroll
                    for (int mt = 0; mt < 2; mt++) {
#pragma unroll
                        for (int hp = 0; hp < 2; hp++) {
                            const int rowl = wm*32 + mt*16 + qr + hp*8;
                            const int q = hp*2;
                            float2 gg = h2f(*(const uint32_t*)&Gs[rowl*PG + g*HH + colg]);
                            if (g == 0) {
                                rv[mt][nt][hp] = f2h(sigf(gg.x + acc[mt][nt][q]   + bb.x),
                                                     sigf(gg.y + acc[mt][nt][q+1] + bb.y));
                            } else if (g == 1) {
                                zv[mt][nt][hp] = f2h(sigf(gg.x + acc[mt][nt][q]   + bb.x),
                                                     sigf(gg.y + acc[mt][nt][q+1] + bb.y));
                            } else {
                                float2 rr = h2f(rv[mt][nt][hp]);
                                float2 zz = h2f(zv[mt][nt][hp]);
                                float2 ho = h2f(*(const uint32_t*)&Hs[rowl*PH + colg]);
                                float nn0 = tanhf(gg.x + rr.x*(acc[mt][nt][q]   + bb.x));
                                float nn1 = tanhf(gg.y + rr.y*(acc[mt][nt][q+1] + bb.y));
                                float h0 = (1.f - zz.x)*nn0 + zz.x*ho.x;
                                float h1 = (1.f - zz.y)*nn1 + zz.y*ho.y;
                                hnew[nc][mt][nt][hp] = f2h(h0, h1);
                                float2 s2 = *(const float2*)(g_s2 + colg);
                                float2 o2 = *(const float2*)(g_o2 + colg);
                                float y0 = fmaf(h0, s2.x, o2.x); y0 = y0>=0.f ? y0 : aA*y0;
                                float y1 = fmaf(h1, s2.y, o2.y); y1 = y1>=0.f ? y1 : aA*y1;
                                *(uint32_t*)(g_hs16 + ((size_t)(m0 + rowl) * LLN + l) * HH + colg) = f2h(y0, y1);
                            }
                        }
                    }
                }
            }
        }
        // ---- commit h_new to smem (after all warps done reading old h) ----
        __syncthreads();
#pragma unroll
        for (int nc = 0; nc < 2; nc++)
#pragma unroll
            for (int nt = 0; nt < 4; nt++) {
                const int colg = nc*128 + wn*32 + nt*8 + 2*qc;
#pragma unroll
                for (int mt = 0; mt < 2; mt++)
#pragma unroll
                    for (int hp = 0; hp < 2; hp++) {
                        const int rowl = wm*32 + mt*16 + qr + hp*8;
                        *(uint32_t*)&Hs[rowl*PH + colg] = hnew[nc][mt][nt][hp];
                    }
            }
        // next pass's first __syncthreads orders these writes before reads
    }
}

// ---------------- launch ----------------------------------------------------
extern "C" void kernel_launch(void* const* d_in, const int* in_sizes, int n_in,
                              void* d_out, int out_size)
{
    const float* A     = (const float*)d_in[0];
    const float* W_lin = (const float*)d_in[1];
    const float* b_lin = (const float*)d_in[2];
    const float* g1    = (const float*)d_in[3];
    const float* be1   = (const float*)d_in[4];
    const float* m1    = (const float*)d_in[5];
    const float* v1    = (const float*)d_in[6];
    const float* a1    = (const float*)d_in[7];
    const float* W_ih  = (const float*)d_in[8];
    const float* W_hh  = (const float*)d_in[9];
    const float* b_ih  = (const float*)d_in[10];
    const float* b_hh  = (const float*)d_in[11];
    const float* g2    = (const float*)d_in[12];
    const float* be2   = (const float*)d_in[13];
    const float* m2    = (const float*)d_in[14];
    const float* v2    = (const float*)d_in[15];
    const float* a2    = (const float*)d_in[16];
    const float* Wc    = (const float*)d_in[17];
    const float* bc    = (const float*)d_in[18];
    const float* g3    = (const float*)d_in[19];
    const float* be3   = (const float*)d_in[20];
    const float* m3    = (const float*)d_in[21];
    const float* v3    = (const float*)d_in[22];
    const float* a3    = (const float*)d_in[23];
    const float* W_mu  = (const float*)d_in[24];
    const float* b_mu  = (const float*)d_in[25];
    float* out = (float*)d_out;

    __half *pxh, *px16, *pgi16, *phs16, *py216;
    __half *pwlin, *pwih, *pwc, *pwmu;
    cudaGetSymbolAddress((void**)&pxh,   g_xh);
    cudaGetSymbolAddress((void**)&px16,  g_x16);
    cudaGetSymbolAddress((void**)&pgi16, g_gi16);
    cudaGetSymbolAddress((void**)&phs16, g_hs16);
    cudaGetSymbolAddress((void**)&py216, g_y216);
    cudaGetSymbolAddress((void**)&pwlin, g_wlin16);
    cudaGetSymbolAddress((void**)&pwih,  g_wih16);
    cudaGetSymbolAddress((void**)&pwc,   g_wc16);
    cudaGetSymbolAddress((void**)&pwmu,  g_wmu16);

    cudaFuncSetAttribute(gru_persist, cudaFuncAttributeMaxDynamicSharedMemorySize, GRUP_SMEM);

    prep_kernel<<<1, 256>>>(g1, be1, m1, v1, a1, g2, be2, m2, v2, a2, g3, be3, m3, v3, a3);

    cvt_kernel<<<(BB*FF/8 + 255)/256, 256>>>(A, pxh, BB*FF/8);
    cvt_w_kernel<<<(CW4 + 255)/256, 256>>>(W_lin, W_ih, W_hh, Wc, W_mu);

    // x = PReLU(BN1(A @ W_lin^T + b_lin)) : [8192,256], K=640
    hgemm3<128,128,4,2,1,true><<<dim3(HH/128, BB/128), 256>>>(pxh, pwlin, b_lin, px16, BB, HH, FF);

    // gi = x @ W_ih^T + b_ih : [8192,768], K=256
    hgemm3<128,128,4,2,0,true><<<dim3(GG/128, BB/128), 256>>>(px16, pwih, b_ih, pgi16, BB, GG, HH);

    // persistent GRU: all 20 steps, one launch
    gru_persist<<<BB/64, 256, GRUP_SMEM>>>(b_hh);

    // y2 = PReLU(BN3(hs_bn2 @ Wc^T + bc)) : [163840,256], K=256
    hgemm3<128,128,4,2,3,true><<<dim3(HH/128, BLM/128), 256>>>(phs16, pwc, bc, py216, BLM, HH, HH);

    // pred = y2 @ W_mu^T + b_mu : [163840,32] fp32 out
    hgemm3<128,32,4,2,0,false><<<dim3(1, BLM/128), 256>>>(py216, pwmu, b_mu, out, BLM, CC, HH);
}

// round 15
// speedup vs baseline: 1.2608x; 1.2608x over previous
#include <cuda_runtime.h>
#include <cuda_fp16.h>
#include <math.h>
#include <stdint.h>

#define EE 64
#define SSZ 128
#define FF 640
#define HH 256
#define GG 768          // 3*H
#define LLN 20
#define CC 32
#define BB (EE*SSZ)     // 8192
#define BLM (BB*LLN)    // 163840
#define EPSV 1e-5f

// ---------------- scratch (static __device__, no allocation) ----------------
__device__ __half g_xh [BB*FF];
__device__ __half g_x16[BB*HH];
__device__ __half g_gi16[BB*GG];
__device__ __half g_gh16[BB*GG];
__device__ __half g_h16[BB*HH];
__device__ __half g_hs16[BLM*HH];   // BN2+PReLU applied
__device__ __half g_y216[BLM*HH];
__device__ __half g_wlin16[HH*FF];
__device__ __half g_wih16[GG*HH];
__device__ __half g_whh16[GG*HH];
__device__ __half g_wc16[HH*HH];
__device__ __half g_wmu16[CC*HH];
__device__ float g_s1[HH], g_o1[HH];
__device__ float g_s2[HH], g_o2[HH];
__device__ float g_s3[HH], g_o3[HH];
__device__ float g_al[3];

// ---------------- helpers ----------------------------------------------------
__device__ __forceinline__ uint32_t cvta_s(const void* p) {
    return (uint32_t)__cvta_generic_to_shared(p);
}
__device__ __forceinline__ void mma16(float* c, const uint32_t* a, const uint32_t* b) {
    asm volatile("mma.sync.aligned.m16n8k16.row.col.f32.f16.f16.f32 "
        "{%0,%1,%2,%3},{%4,%5,%6,%7},{%8,%9},{%0,%1,%2,%3};"
        : "+f"(c[0]), "+f"(c[1]), "+f"(c[2]), "+f"(c[3])
        : "r"(a[0]), "r"(a[1]), "r"(a[2]), "r"(a[3]), "r"(b[0]), "r"(b[1]));
}
#define LDSM4(r0,r1,r2,r3,addr) \
    asm volatile("ldmatrix.sync.aligned.m8n8.x4.shared.b16 {%0,%1,%2,%3}, [%4];" \
        : "=r"(r0),"=r"(r1),"=r"(r2),"=r"(r3) : "r"(addr))
#define CP_ASYNC16(dst, src) \
    asm volatile("cp.async.ca.shared.global [%0], [%1], 16;" :: "r"(dst), "l"(src))
#define CP_COMMIT() asm volatile("cp.async.commit_group;" ::)
#define CP_WAIT2()  asm volatile("cp.async.wait_group 2;" ::)

__device__ __forceinline__ float sigf(float x) { return 1.f / (1.f + expf(-x)); }
__device__ __forceinline__ float2 h2f(uint32_t u) { return __half22float2(*(__half2*)&u); }
__device__ __forceinline__ uint32_t f2h(float a, float b) {
    __half2 h = __floats2half2_rn(a, b); return *(uint32_t*)&h;
}

// ---------------- prep ------------------------------------------------------
__global__ void prep_kernel(const float* g1,const float* b1,const float* m1,const float* v1,const float* a1,
                            const float* g2,const float* b2,const float* m2,const float* v2,const float* a2,
                            const float* g3,const float* b3,const float* m3,const float* v3,const float* a3)
{
    int i = threadIdx.x;
    float s;
    s = g1[i] / sqrtf(v1[i] + EPSV); g_s1[i] = s; g_o1[i] = b1[i] - m1[i]*s;
    s = g2[i] / sqrtf(v2[i] + EPSV); g_s2[i] = s; g_o2[i] = b2[i] - m2[i]*s;
    s = g3[i] / sqrtf(v3[i] + EPSV); g_s3[i] = s; g_o3[i] = b3[i] - m3[i]*s;
    if (i == 0) { g_al[0] = a1[0]; g_al[1] = a2[0]; g_al[2] = a3[0]; }
}

__global__ void cvt_kernel(const float* __restrict__ s, __half* __restrict__ d, int n8)
{
    int i = blockIdx.x * blockDim.x + threadIdx.x;
    if (i >= n8) return;
    float4 v0 = *(const float4*)(s + i*8);
    float4 v1 = *(const float4*)(s + i*8 + 4);
    *(uint4*)(d + i*8) = make_uint4(f2h(v0.x,v0.y), f2h(v0.z,v0.w), f2h(v1.x,v1.y), f2h(v1.z,v1.w));
}

#define CW0 (HH*FF/8)
#define CW1 (CW0 + GG*HH/8)
#define CW2 (CW1 + GG*HH/8)
#define CW3 (CW2 + HH*HH/8)
#define CW4 (CW3 + CC*HH/8)
__global__ void cvt_w_kernel(const float* wlin, const float* wih, const float* whh,
                             const float* wc, const float* wmu)
{
    int i = blockIdx.x * blockDim.x + threadIdx.x;
    if (i >= CW4) return;
    const float* s; __half* d; int j;
    if (i < CW0)      { s = wlin; d = g_wlin16; j = i; }
    else if (i < CW1) { s = wih;  d = g_wih16;  j = i - CW0; }
    else if (i < CW2) { s = whh;  d = g_whh16;  j = i - CW1; }
    else if (i < CW3) { s = wc;   d = g_wc16;   j = i - CW2; }
    else              { s = wmu;  d = g_wmu16;  j = i - CW3; }
    float4 v0 = *(const float4*)(s + (size_t)j*8);
    float4 v1 = *(const float4*)(s + (size_t)j*8 + 4);
    *(uint4*)(d + (size_t)j*8) = make_uint4(f2h(v0.x,v0.y), f2h(v0.z,v0.w), f2h(v1.x,v1.y), f2h(v1.z,v1.w));
}

__global__ void zero_h_kernel()
{
    int i = blockIdx.x * blockDim.x + threadIdx.x;   // BB*HH/8
    *(uint4*)(g_h16 + (size_t)i*8) = make_uint4(0,0,0,0);
}

// ---------------- fp16 GEMM, 4-stage cp.async, single sync per tile ----------
// C = epi(A @ W^T + bias). A:[M,K], W:[N,K] fp16 row-major. BK=32, pitch 40.
// MODE 0: bias. MODE 1: bias+BN1+PReLU. MODE 3: bias+BN3+PReLU.
template<int BM,int BN,int WM,int WN,int MODE,bool OUTH>
__global__ __launch_bounds__(256, 2) void hgemm4(
    const __half* __restrict__ A, const __half* __restrict__ W,
    const float* __restrict__ bias, void* __restrict__ Cst,
    int M, int N, int K)
{
    constexpr int PIT = 40;
    constexpr int ST  = 4;
    extern __shared__ __half smh[];
    __half* Ah = smh;                       // [ST][BM*PIT]
    __half* Wh = smh + ST*BM*PIT;           // [ST][BN*PIT]

    const int tid  = threadIdx.x;
    const int wid  = tid >> 5;
    const int lane = tid & 31;
    const int wm   = wid % WM;
    const int wn   = wid / WM;
    constexpr int WTM = BM / WM;
    constexpr int WTN = BN / WN;
    constexpr int MT  = WTM / 16;
    constexpr int NT  = WTN / 8;
    const int qr = lane >> 2, qc = lane & 3;
    const int l8 = lane & 7;

    const int m0 = blockIdx.y * BM;
    const int n0 = blockIdx.x * BN;

    constexpr int ACH = BM * 4;
    constexpr int WCH = BN * 4;
    constexpr int AIT = ACH / 256;
    constexpr int WIT = (WCH + 255) / 256;

    float acc[MT][NT][4];
#pragma unroll
    for (int i = 0; i < MT; i++)
#pragma unroll
        for (int j = 0; j < NT; j++)
#pragma unroll
            for (int q = 0; q < 4; q++) acc[i][j][q] = 0.f;

    const int T = K / 32;

#define ISSUE_STAGE(st, t) do { \
        _Pragma("unroll") \
        for (int it = 0; it < AIT; it++) { \
            int idx = tid + it*256; int r = idx >> 2, c = idx & 3; \
            uint32_t ds = cvta_s(&Ah[(st)*BM*PIT + r*PIT + c*8]); \
            CP_ASYNC16(ds, A + (size_t)(m0 + r) * K + (size_t)(t)*32 + c*8); \
        } \
        _Pragma("unroll") \
        for (int it = 0; it < WIT; it++) { \
            int idx = tid + it*256; \
            if ((WCH % 256 == 0) || idx < WCH) { \
                int r = idx >> 2, c = idx & 3; \
                uint32_t ds = cvta_s(&Wh[(st)*BN*PIT + r*PIT + c*8]); \
                CP_ASYNC16(ds, W + (size_t)(n0 + r) * K + (size_t)(t)*32 + c*8); \
            } \
        } \
        CP_COMMIT(); \
    } while (0)

    // prologue: stages 0..2 in flight (3 groups)
    ISSUE_STAGE(0, 0);
    if (T > 1) { ISSUE_STAGE(1, 1); } else { CP_COMMIT(); }
    if (T > 2) { ISSUE_STAGE(2, 2); } else { CP_COMMIT(); }

    for (int t = 0; t < T; t++) {
        CP_WAIT2();                // stage t retired (3 in flight -> wait to 2)
        __syncthreads();           // all warps see stage t; reads of stage t-1 done

        if (t + 3 < T) { ISSUE_STAGE((t + 3) & 3, t + 3); } else { CP_COMMIT(); }

        const int buf = t & 3;
        const __half* Ab = Ah + buf*BM*PIT;
        const __half* Wb = Wh + buf*BN*PIT;

#pragma unroll
        for (int ks = 0; ks < 2; ks++) {
            uint32_t af[MT][4], bf[NT][2];
#pragma unroll
            for (int mt = 0; mt < MT; mt++) {
                const int m  = wm*WTM + mt*16 + l8 + ((lane >> 3) & 1) * 8;
                const int ck = 2*ks + (lane >> 4);
                uint32_t ad = cvta_s(&Ab[m*PIT + ck*8]);
                LDSM4(af[mt][0], af[mt][1], af[mt][2], af[mt][3], ad);
            }
#pragma unroll
            for (int np = 0; np < NT/2; np++) {
                const int n  = wn*WTN + np*16 + l8 + ((lane >> 4) & 1) * 8;
                const int ck = 2*ks + ((lane >> 3) & 1);
                uint32_t bd = cvta_s(&Wb[n*PIT + ck*8]);
                LDSM4(bf[2*np][0], bf[2*np][1], bf[2*np+1][0], bf[2*np+1][1], bd);
            }
#pragma unroll
            for (int mt = 0; mt < MT; mt++)
#pragma unroll
                for (int nt = 0; nt < NT; nt++)
                    mma16(acc[mt][nt], af[mt], bf[nt]);
        }
    }

    // ---- epilogue ----
#pragma unroll
    for (int mt = 0; mt < MT; mt++) {
#pragma unroll
        for (int nt = 0; nt < NT; nt++) {
            const int row = m0 + wm*WTM + mt*16 + qr;
            const int col = n0 + wn*WTN + nt*8 + 2*qc;
            float2 bv = *(const float2*)(bias + col);
            float x0 = acc[mt][nt][0] + bv.x;
            float x1 = acc[mt][nt][1] + bv.y;
            float x2 = acc[mt][nt][2] + bv.x;
            float x3 = acc[mt][nt][3] + bv.y;
            if (MODE == 1 || MODE == 3) {
                const float* sp = (MODE == 1) ? g_s1 : g_s3;
                const float* op = (MODE == 1) ? g_o1 : g_o3;
                const float al  = (MODE == 1) ? g_al[0] : g_al[2];
                float2 sv = *(const float2*)(sp + col);
                float2 ov = *(const float2*)(op + col);
                x0 = fmaf(x0, sv.x, ov.x); x0 = x0>=0.f ? x0 : al*x0;
                x1 = fmaf(x1, sv.y, ov.y); x1 = x1>=0.f ? x1 : al*x1;
                x2 = fmaf(x2, sv.x, ov.x); x2 = x2>=0.f ? x2 : al*x2;
                x3 = fmaf(x3, sv.y, ov.y); x3 = x3>=0.f ? x3 : al*x3;
            }
            if (OUTH) {
                __half* C = (__half*)Cst;
                *(uint32_t*)&C[(size_t)row * N + col]       = f2h(x0, x1);
                *(uint32_t*)&C[(size_t)(row + 8) * N + col] = f2h(x2, x3);
            } else {
                float* C = (float*)Cst;
                *(float2*)&C[(size_t)row * N + col]       = make_float2(x0, x1);
                *(float2*)&C[(size_t)(row + 8) * N + col] = make_float2(x2, x3);
            }
        }
    }
#undef ISSUE_STAGE
}

// ---------------- GRU gate elementwise step (fp16 I/O) ----------------------
__global__ void gate16_kernel(int l)
{
    int idx = blockIdx.x * blockDim.x + threadIdx.x;   // over BB*HH/8
    int j8 = idx % (HH/8);
    int b  = idx / (HH/8);
    const __half* gp = g_gi16 + (size_t)b * GG + j8*8;
    const __half* hp = g_gh16 + (size_t)b * GG + j8*8;

    uint4 gir = *(const uint4*)(gp);
    uint4 giz = *(const uint4*)(gp + HH);
    uint4 gin = *(const uint4*)(gp + 2*HH);
    uint4 ghr = *(const uint4*)(hp);
    uint4 ghz = *(const uint4*)(hp + HH);
    uint4 ghn = *(const uint4*)(hp + 2*HH);
    uint4 hv  = *(const uint4*)(g_h16 + (size_t)b * HH + j8*8);

    float4 s20 = *(const float4*)(g_s2 + j8*8);
    float4 s21 = *(const float4*)(g_s2 + j8*8 + 4);
    float4 o20 = *(const float4*)(g_o2 + j8*8);
    float4 o21 = *(const float4*)(g_o2 + j8*8 + 4);
    const float aA = g_al[1];

    uint32_t ho[4], yo[4];
    const uint32_t* girp = (const uint32_t*)&gir;
    const uint32_t* gizp = (const uint32_t*)&giz;
    const uint32_t* ginp = (const uint32_t*)&gin;
    const uint32_t* ghrp = (const uint32_t*)&ghr;
    const uint32_t* ghzp = (const uint32_t*)&ghz;
    const uint32_t* ghnp = (const uint32_t*)&ghn;
    const uint32_t* hvp  = (const uint32_t*)&hv;
    const float s2a[8] = {s20.x,s20.y,s20.z,s20.w,s21.x,s21.y,s21.z,s21.w};
    const float o2a[8] = {o20.x,o20.y,o20.z,o20.w,o21.x,o21.y,o21.z,o21.w};

#pragma unroll
    for (int p = 0; p < 4; p++) {
        float2 gr = h2f(girp[p]), gz = h2f(gizp[p]), gn = h2f(ginp[p]);
        float2 hr = h2f(ghrp[p]), hz = h2f(ghzp[p]), hn = h2f(ghnp[p]);
        float2 h0 = h2f(hvp[p]);
        float r0 = sigf(gr.x + hr.x), r1 = sigf(gr.y + hr.y);
        float z0 = sigf(gz.x + hz.x), z1 = sigf(gz.y + hz.y);
        float n0 = tanhf(gn.x + r0*hn.x), n1 = tanhf(gn.y + r1*hn.y);
        float hx = (1.f - z0)*n0 + z0*h0.x;
        float hy = (1.f - z1)*n1 + z1*h0.y;
        ho[p] = f2h(hx, hy);
        float yx = fmaf(hx, s2a[2*p],   o2a[2*p]);   yx = yx>=0.f ? yx : aA*yx;
        float yy = fmaf(hy, s2a[2*p+1], o2a[2*p+1]); yy = yy>=0.f ? yy : aA*yy;
        yo[p] = f2h(yx, yy);
    }
    *(uint4*)(g_h16 + (size_t)b * HH + j8*8) = *(uint4*)ho;
    *(uint4*)(g_hs16 + ((size_t)b * LLN + l) * HH + j8*8) = *(uint4*)yo;
}

// ---------------- launch ----------------------------------------------------
#define SMEM_BN128 (4*(128*40 + 128*40)*2)   // 81920
#define SMEM_BN32  (4*(128*40 + 32*40)*2)    // 51200

extern "C" void kernel_launch(void* const* d_in, const int* in_sizes, int n_in,
                              void* d_out, int out_size)
{
    const float* A     = (const float*)d_in[0];
    const float* W_lin = (const float*)d_in[1];
    const float* b_lin = (const float*)d_in[2];
    const float* g1    = (const float*)d_in[3];
    const float* be1   = (const float*)d_in[4];
    const float* m1    = (const float*)d_in[5];
    const float* v1    = (const float*)d_in[6];
    const float* a1    = (const float*)d_in[7];
    const float* W_ih  = (const float*)d_in[8];
    const float* W_hh  = (const float*)d_in[9];
    const float* b_ih  = (const float*)d_in[10];
    const float* b_hh  = (const float*)d_in[11];
    const float* g2    = (const float*)d_in[12];
    const float* be2   = (const float*)d_in[13];
    const float* m2    = (const float*)d_in[14];
    const float* v2    = (const float*)d_in[15];
    const float* a2    = (const float*)d_in[16];
    const float* Wc    = (const float*)d_in[17];
    const float* bc    = (const float*)d_in[18];
    const float* g3    = (const float*)d_in[19];
    const float* be3   = (const float*)d_in[20];
    const float* m3    = (const float*)d_in[21];
    const float* v3    = (const float*)d_in[22];
    const float* a3    = (const float*)d_in[23];
    const float* W_mu  = (const float*)d_in[24];
    const float* b_mu  = (const float*)d_in[25];
    float* out = (float*)d_out;

    __half *pxh, *px16, *pgi16, *pgh16, *ph16, *phs16, *py216;
    __half *pwlin, *pwih, *pwhh, *pwc, *pwmu;
    cudaGetSymbolAddress((void**)&pxh,   g_xh);
    cudaGetSymbolAddress((void**)&px16,  g_x16);
    cudaGetSymbolAddress((void**)&pgi16, g_gi16);
    cudaGetSymbolAddress((void**)&pgh16, g_gh16);
    cudaGetSymbolAddress((void**)&ph16,  g_h16);
    cudaGetSymbolAddress((void**)&phs16, g_hs16);
    cudaGetSymbolAddress((void**)&py216, g_y216);
    cudaGetSymbolAddress((void**)&pwlin, g_wlin16);
    cudaGetSymbolAddress((void**)&pwih,  g_wih16);
    cudaGetSymbolAddress((void**)&pwhh,  g_whh16);
    cudaGetSymbolAddress((void**)&pwc,   g_wc16);
    cudaGetSymbolAddress((void**)&pwmu,  g_wmu16);

    cudaFuncSetAttribute(hgemm4<128,128,4,2,1,true>, cudaFuncAttributeMaxDynamicSharedMemorySize, SMEM_BN128);
    cudaFuncSetAttribute(hgemm4<128,128,4,2,0,true>, cudaFuncAttributeMaxDynamicSharedMemorySize, SMEM_BN128);
    cudaFuncSetAttribute(hgemm4<128,128,4,2,3,true>, cudaFuncAttributeMaxDynamicSharedMemorySize, SMEM_BN128);
    cudaFuncSetAttribute(hgemm4<128,32,4,2,0,false>, cudaFuncAttributeMaxDynamicSharedMemorySize, SMEM_BN32);

    prep_kernel<<<1, 256>>>(g1, be1, m1, v1, a1, g2, be2, m2, v2, a2, g3, be3, m3, v3, a3);
    zero_h_kernel<<<(BB*HH/8)/256, 256>>>();

    cvt_kernel<<<(BB*FF/8 + 255)/256, 256>>>(A, pxh, BB*FF/8);
    cvt_w_kernel<<<(CW4 + 255)/256, 256>>>(W_lin, W_ih, W_hh, Wc, W_mu);

    // x = PReLU(BN1(A @ W_lin^T + b_lin)) : [8192,256], K=640
    hgemm4<128,128,4,2,1,true><<<dim3(HH/128, BB/128), 256, SMEM_BN128>>>(pxh, pwlin, b_lin, px16, BB, HH, FF);

    // gi = x @ W_ih^T + b_ih : [8192,768], K=256
    hgemm4<128,128,4,2,0,true><<<dim3(GG/128, BB/128), 256, SMEM_BN128>>>(px16, pwih, b_ih, pgi16, BB, GG, HH);

    // GRU recurrence
    for (int l = 0; l < LLN; l++) {
        hgemm4<128,128,4,2,0,true><<<dim3(GG/128, BB/128), 256, SMEM_BN128>>>(ph16, pwhh, b_hh, pgh16, BB, GG, HH);
        gate16_kernel<<<(BB*HH/8)/256, 256>>>(l);
    }

    // y2 = PReLU(BN3(hs_bn2 @ Wc^T + bc)) : [163840,256], K=256
    hgemm4<128,128,4,2,3,true><<<dim3(HH/128, BLM/128), 256, SMEM_BN128>>>(phs16, pwc, bc, py216, BLM, HH, HH);

    // pred = y2 @ W_mu^T + b_mu : [163840,32] fp32 out
    hgemm4<128,32,4,2,0,false><<<dim3(1, BLM/128), 256, SMEM_BN32>>>(py216, pwmu, b_mu, out, BLM, CC, HH);
}

// round 16
// speedup vs baseline: 1.3281x; 1.0533x over previous
#include <cuda_runtime.h>
#include <cuda_fp16.h>
#include <math.h>
#include <stdint.h>

#define EE 64
#define SSZ 128
#define FF 640
#define HH 256
#define GG 768          // 3*H
#define LLN 20
#define CC 32
#define BB (EE*SSZ)     // 8192
#define BLM (BB*LLN)    // 163840
#define EPSV 1e-5f

// ---------------- scratch (static __device__, no allocation) ----------------
__device__ __half g_xh [BB*FF];
__device__ __half g_x16[BB*HH];
__device__ __half g_gi16[BB*GG];    // PACKED column order
__device__ __half g_ha16[BB*HH];    // h ping
__device__ __half g_hb16[BB*HH];    // h pong
__device__ __half g_hs16[BLM*HH];   // BN2+PReLU applied
__device__ __half g_y216[BLM*HH];
__device__ __half g_wlin16[HH*FF];
__device__ __half g_wih16[GG*HH];   // PACKED rows
__device__ __half g_whh16[GG*HH];   // PACKED rows
__device__ __half g_wc16[HH*HH];
__device__ __half g_wmu16[CC*HH];
__device__ float g_bip[GG], g_bhp[GG];   // packed biases
__device__ float g_s1[HH], g_o1[HH];
__device__ float g_s2[HH], g_o2[HH];
__device__ float g_s3[HH], g_o3[HH];
__device__ float g_al[3];

// ---------------- helpers ----------------------------------------------------
__device__ __forceinline__ uint32_t cvta_s(const void* p) {
    return (uint32_t)__cvta_generic_to_shared(p);
}
__device__ __forceinline__ void mma16(float* c, const uint32_t* a, const uint32_t* b) {
    asm volatile("mma.sync.aligned.m16n8k16.row.col.f32.f16.f16.f32 "
        "{%0,%1,%2,%3},{%4,%5,%6,%7},{%8,%9},{%0,%1,%2,%3};"
        : "+f"(c[0]), "+f"(c[1]), "+f"(c[2]), "+f"(c[3])
        : "r"(a[0]), "r"(a[1]), "r"(a[2]), "r"(a[3]), "r"(b[0]), "r"(b[1]));
}
#define LDSM4(r0,r1,r2,r3,addr) \
    asm volatile("ldmatrix.sync.aligned.m8n8.x4.shared.b16 {%0,%1,%2,%3}, [%4];" \
        : "=r"(r0),"=r"(r1),"=r"(r2),"=r"(r3) : "r"(addr))
#define CP_ASYNC16(dst, src) \
    asm volatile("cp.async.ca.shared.global [%0], [%1], 16;" :: "r"(dst), "l"(src))
#define CP_COMMIT() asm volatile("cp.async.commit_group;" ::)
#define CP_WAIT2()  asm volatile("cp.async.wait_group 2;" ::)

__device__ __forceinline__ float sigf(float x) { return 1.f / (1.f + expf(-x)); }
__device__ __forceinline__ float2 h2f(uint32_t u) { return __half22float2(*(__half2*)&u); }
__device__ __forceinline__ uint32_t f2h(float a, float b) {
    __half2 h = __floats2half2_rn(a, b); return *(uint32_t*)&h;
}

// ---------------- prep ------------------------------------------------------
__global__ void prep_kernel(const float* g1,const float* b1,const float* m1,const float* v1,const float* a1,
                            const float* g2,const float* b2,const float* m2,const float* v2,const float* a2,
                            const float* g3,const float* b3,const float* m3,const float* v3,const float* a3,
                            const float* bih, const float* bhh)
{
    int i = threadIdx.x;
    float s;
    s = g1[i] / sqrtf(v1[i] + EPSV); g_s1[i] = s; g_o1[i] = b1[i] - m1[i]*s;
    s = g2[i] / sqrtf(v2[i] + EPSV); g_s2[i] = s; g_o2[i] = b2[i] - m2[i]*s;
    s = g3[i] / sqrtf(v3[i] + EPSV); g_s3[i] = s; g_o3[i] = b3[i] - m3[i]*s;
    if (i == 0) { g_al[0] = a1[0]; g_al[1] = a2[0]; g_al[2] = a3[0]; }
    // packed bias: p = T*24 + g*8 + v  ->  src g*256 + T*8 + v
#pragma unroll
    for (int k = 0; k < 3; k++) {
        int p = i + k*256;
        int T = p / 24, rem = p % 24, g = rem >> 3, v = rem & 7;
        int src = g*HH + T*8 + v;
        g_bip[p] = bih[src];
        g_bhp[p] = bhh[src];
    }
}

__global__ void cvt_kernel(const float* __restrict__ s, __half* __restrict__ d, int n8)
{
    int i = blockIdx.x * blockDim.x + threadIdx.x;
    if (i >= n8) return;
    float4 v0 = *(const float4*)(s + i*8);
    float4 v1 = *(const float4*)(s + i*8 + 4);
    *(uint4*)(d + i*8) = make_uint4(f2h(v0.x,v0.y), f2h(v0.z,v0.w), f2h(v1.x,v1.y), f2h(v1.z,v1.w));
}

#define CW0 (HH*FF/8)
#define CW1 (CW0 + GG*HH/8)
#define CW2 (CW1 + GG*HH/8)
#define CW3 (CW2 + HH*HH/8)
#define CW4 (CW3 + CC*HH/8)
__global__ void cvt_w_kernel(const float* wlin, const float* wih, const float* whh,
                             const float* wc, const float* wmu)
{
    int i = blockIdx.x * blockDim.x + threadIdx.x;
    if (i >= CW4) return;
    const float* s; __half* d; size_t sj, dj;
    if (i < CW0)      { s = wlin; d = g_wlin16; sj = dj = (size_t)i; }
    else if (i < CW2) {
        // packed W_ih / W_hh: dest row pr -> src row g*256 + T*8 + v
        int j = (i < CW1) ? (i - CW0) : (i - CW1);
        s = (i < CW1) ? wih : whh;
        d = (i < CW1) ? g_wih16 : g_whh16;
        int pr = j >> 5, jc = j & 31;            // 32 chunks per 256-wide row
        int T = pr / 24, rem = pr % 24, g = rem >> 3, v = rem & 7;
        sj = (size_t)(g*HH + T*8 + v) * 32 + jc;
        dj = (size_t)j;
    }
    else if (i < CW3) { s = wc;  d = g_wc16;  sj = dj = (size_t)(i - CW2); }
    else              { s = wmu; d = g_wmu16; sj = dj = (size_t)(i - CW3); }
    float4 v0 = *(const float4*)(s + sj*8);
    float4 v1 = *(const float4*)(s + sj*8 + 4);
    *(uint4*)(d + dj*8) = make_uint4(f2h(v0.x,v0.y), f2h(v0.z,v0.w), f2h(v1.x,v1.y), f2h(v1.z,v1.w));
}

__global__ void zero_h_kernel()
{
    int i = blockIdx.x * blockDim.x + threadIdx.x;   // BB*HH/8
    *(uint4*)(g_ha16 + (size_t)i*8) = make_uint4(0,0,0,0);
}

// ---------------- fp16 GEMM, 4-stage cp.async (R15, unchanged) ---------------
template<int BM,int BN,int WM,int WN,int MODE,bool OUTH>
__global__ __launch_bounds__(256, 2) void hgemm4(
    const __half* __restrict__ A, const __half* __restrict__ W,
    const float* __restrict__ bias, void* __restrict__ Cst,
    int M, int N, int K)
{
    constexpr int PIT = 40;
    constexpr int ST  = 4;
    extern __shared__ __half smh[];
    __half* Ah = smh;
    __half* Wh = smh + ST*BM*PIT;

    const int tid  = threadIdx.x;
    const int wid  = tid >> 5;
    const int lane = tid & 31;
    const int wm   = wid % WM;
    const int wn   = wid / WM;
    constexpr int WTM = BM / WM;
    constexpr int WTN = BN / WN;
    constexpr int MT  = WTM / 16;
    constexpr int NT  = WTN / 8;
    const int qr = lane >> 2, qc = lane & 3;
    const int l8 = lane & 7;

    const int m0 = blockIdx.y * BM;
    const int n0 = blockIdx.x * BN;

    constexpr int ACH = BM * 4;
    constexpr int WCH = BN * 4;
    constexpr int AIT = ACH / 256;
    constexpr int WIT = (WCH + 255) / 256;

    float acc[MT][NT][4];
#pragma unroll
    for (int i = 0; i < MT; i++)
#pragma unroll
        for (int j = 0; j < NT; j++)
#pragma unroll
            for (int q = 0; q < 4; q++) acc[i][j][q] = 0.f;

    const int T = K / 32;

#define ISSUE_STAGE(st, t) do { \
        _Pragma("unroll") \
        for (int it = 0; it < AIT; it++) { \
            int idx = tid + it*256; int r = idx >> 2, c = idx & 3; \
            uint32_t ds = cvta_s(&Ah[(st)*BM*PIT + r*PIT + c*8]); \
            CP_ASYNC16(ds, A + (size_t)(m0 + r) * K + (size_t)(t)*32 + c*8); \
        } \
        _Pragma("unroll") \
        for (int it = 0; it < WIT; it++) { \
            int idx = tid + it*256; \
            if ((WCH % 256 == 0) || idx < WCH) { \
                int r = idx >> 2, c = idx & 3; \
                uint32_t ds = cvta_s(&Wh[(st)*BN*PIT + r*PIT + c*8]); \
                CP_ASYNC16(ds, W + (size_t)(n0 + r) * K + (size_t)(t)*32 + c*8); \
            } \
        } \
        CP_COMMIT(); \
    } while (0)

    ISSUE_STAGE(0, 0);
    if (T > 1) { ISSUE_STAGE(1, 1); } else { CP_COMMIT(); }
    if (T > 2) { ISSUE_STAGE(2, 2); } else { CP_COMMIT(); }

    for (int t = 0; t < T; t++) {
        CP_WAIT2();
        __syncthreads();
        if (t + 3 < T) { ISSUE_STAGE((t + 3) & 3, t + 3); } else { CP_COMMIT(); }

        const int buf = t & 3;
        const __half* Ab = Ah + buf*BM*PIT;
        const __half* Wb = Wh + buf*BN*PIT;

#pragma unroll
        for (int ks = 0; ks < 2; ks++) {
            uint32_t af[MT][4], bf[NT][2];
#pragma unroll
            for (int mt = 0; mt < MT; mt++) {
                const int m  = wm*WTM + mt*16 + l8 + ((lane >> 3) & 1) * 8;
                const int ck = 2*ks + (lane >> 4);
                uint32_t ad = cvta_s(&Ab[m*PIT + ck*8]);
                LDSM4(af[mt][0], af[mt][1], af[mt][2], af[mt][3], ad);
            }
#pragma unroll
            for (int np = 0; np < NT/2; np++) {
                const int n  = wn*WTN + np*16 + l8 + ((lane >> 4) & 1) * 8;
                const int ck = 2*ks + ((lane >> 3) & 1);
                uint32_t bd = cvta_s(&Wb[n*PIT + ck*8]);
                LDSM4(bf[2*np][0], bf[2*np][1], bf[2*np+1][0], bf[2*np+1][1], bd);
            }
#pragma unroll
            for (int mt = 0; mt < MT; mt++)
#pragma unroll
                for (int nt = 0; nt < NT; nt++)
                    mma16(acc[mt][nt], af[mt], bf[nt]);
        }
    }

#pragma unroll
    for (int mt = 0; mt < MT; mt++) {
#pragma unroll
        for (int nt = 0; nt < NT; nt++) {
            const int row = m0 + wm*WTM + mt*16 + qr;
            const int col = n0 + wn*WTN + nt*8 + 2*qc;
            float2 bv = *(const float2*)(bias + col);
            float x0 = acc[mt][nt][0] + bv.x;
            float x1 = acc[mt][nt][1] + bv.y;
            float x2 = acc[mt][nt][2] + bv.x;
            float x3 = acc[mt][nt][3] + bv.y;
            if (MODE == 1 || MODE == 3) {
                const float* sp = (MODE == 1) ? g_s1 : g_s3;
                const float* op = (MODE == 1) ? g_o1 : g_o3;
                const float al  = (MODE == 1) ? g_al[0] : g_al[2];
                float2 sv = *(const float2*)(sp + col);
                float2 ov = *(const float2*)(op + col);
                x0 = fmaf(x0, sv.x, ov.x); x0 = x0>=0.f ? x0 : al*x0;
                x1 = fmaf(x1, sv.y, ov.y); x1 = x1>=0.f ? x1 : al*x1;
                x2 = fmaf(x2, sv.x, ov.x); x2 = x2>=0.f ? x2 : al*x2;
                x3 = fmaf(x3, sv.y, ov.y); x3 = x3>=0.f ? x3 : al*x3;
            }
            if (OUTH) {
                __half* C = (__half*)Cst;
                *(uint32_t*)&C[(size_t)row * N + col]       = f2h(x0, x1);
                *(uint32_t*)&C[(size_t)(row + 8) * N + col] = f2h(x2, x3);
            } else {
                float* C = (float*)Cst;
                *(float2*)&C[(size_t)row * N + col]       = make_float2(x0, x1);
                *(float2*)&C[(size_t)(row + 8) * N + col] = make_float2(x2, x3);
            }
        }
    }
#undef ISSUE_STAGE
}

// ---------------- fused GRU step: BN=96 packed GEMM + gate epilogue ----------
// Tile 128 x 96 over packed W_hh (4 triples = 32 units). Same 4-stage pipeline.
// acc[mt][3*tt+g][q] holds r/z/n of the SAME unit -> full cell in epilogue.
#define GRU_ST 4
#define GRU_SMEM (GRU_ST*(128*40 + 96*40)*2)    // 71680

__global__ __launch_bounds__(256, 2) void gru_gemm(
    const __half* __restrict__ hin, __half* __restrict__ hout, int l)
{
    constexpr int PIT = 40;
    extern __shared__ __half smh[];
    __half* Ah = smh;                        // [4][128*40]
    __half* Wh = smh + GRU_ST*128*PIT;       // [4][96*40]

    const int tid  = threadIdx.x;
    const int wid  = tid >> 5;
    const int lane = tid & 31;
    const int wm   = wid % 4;                // WTM=32, MT=2
    const int wn   = wid / 4;                // WTN=48, NT=6
    const int qr = lane >> 2, qc = lane & 3;
    const int l8 = lane & 7;

    const int m0 = blockIdx.y * 128;
    const int n0 = blockIdx.x * 96;
    const __half* W = g_whh16;

    float acc[2][6][4];
#pragma unroll
    for (int i = 0; i < 2; i++)
#pragma unroll
        for (int j = 0; j < 6; j++)
#pragma unroll
            for (int q = 0; q < 4; q++) acc[i][j][q] = 0.f;

#define GISSUE(st, t) do { \
        _Pragma("unroll") \
        for (int it = 0; it < 2; it++) { \
            int idx = tid + it*256; int r = idx >> 2, c = idx & 3; \
            uint32_t ds = cvta_s(&Ah[(st)*128*PIT + r*PIT + c*8]); \
            CP_ASYNC16(ds, hin + (size_t)(m0 + r) * HH + (size_t)(t)*32 + c*8); \
        } \
        { \
            int idx = tid; int r = idx >> 2, c = idx & 3; \
            uint32_t ds = cvta_s(&Wh[(st)*96*PIT + r*PIT + c*8]); \
            CP_ASYNC16(ds, W + (size_t)(n0 + r) * HH + (size_t)(t)*32 + c*8); \
        } \
        if (tid < 128) { \
            int idx = tid + 256; int r = idx >> 2, c = idx & 3; \
            uint32_t ds = cvta_s(&Wh[(st)*96*PIT + r*PIT + c*8]); \
            CP_ASYNC16(ds, W + (size_t)(n0 + r) * HH + (size_t)(t)*32 + c*8); \
        } \
        CP_COMMIT(); \
    } while (0)

    GISSUE(0, 0); GISSUE(1, 1); GISSUE(2, 2);

    for (int t = 0; t < 8; t++) {            // K=256
        CP_WAIT2();
        __syncthreads();
        if (t + 3 < 8) { GISSUE((t + 3) & 3, t + 3); } else { CP_COMMIT(); }

        const int buf = t & 3;
        const __half* Ab = Ah + buf*128*PIT;
        const __half* Wb = Wh + buf*96*PIT;

#pragma unroll
        for (int ks = 0; ks < 2; ks++) {
            uint32_t af[2][4], bf[6][2];
#pragma unroll
            for (int mt = 0; mt < 2; mt++) {
                const int m  = wm*32 + mt*16 + l8 + ((lane >> 3) & 1) * 8;
                const int ck = 2*ks + (lane >> 4);
                uint32_t ad = cvta_s(&Ab[m*PIT + ck*8]);
                LDSM4(af[mt][0], af[mt][1], af[mt][2], af[mt][3], ad);
            }
#pragma unroll
            for (int np = 0; np < 3; np++) {
                const int n  = wn*48 + np*16 + l8 + ((lane >> 4) & 1) * 8;
                const int ck = 2*ks + ((lane >> 3) & 1);
                uint32_t bd = cvta_s(&Wb[n*PIT + ck*8]);
                LDSM4(bf[2*np][0], bf[2*np][1], bf[2*np+1][0], bf[2*np+1][1], bd);
            }
#pragma unroll
            for (int mt = 0; mt < 2; mt++)
#pragma unroll
                for (int nt = 0; nt < 6; nt++)
                    mma16(acc[mt][nt], af[mt], bf[nt]);
        }
    }

    // ---- GRU cell epilogue ----
    const int ub = blockIdx.x * 32;
    const float aA = g_al[1];
#pragma unroll
    for (int tt = 0; tt < 2; tt++) {
        const int ucol = ub + (wn*2 + tt)*8 + 2*qc;       // unit column pair
        const int cr   = n0 + wn*48 + tt*24 + 2*qc;       // packed col of r-gate
        float2 s2 = *(const float2*)(g_s2 + ucol);
        float2 o2 = *(const float2*)(g_o2 + ucol);
        float2 br = *(const float2*)(g_bhp + cr);
        float2 bz = *(const float2*)(g_bhp + cr + 8);
        float2 bn = *(const float2*)(g_bhp + cr + 16);
#pragma unroll
        for (int mt = 0; mt < 2; mt++) {
#pragma unroll
            for (int hp = 0; hp < 2; hp++) {
                const size_t row = m0 + wm*32 + mt*16 + qr + hp*8;
                const int q = hp*2;
                const __half* gp = g_gi16 + row*GG + cr;
                float2 gr = h2f(*(const uint32_t*)(gp));
                float2 gz = h2f(*(const uint32_t*)(gp + 8));
                float2 gn = h2f(*(const uint32_t*)(gp + 16));
                float2 ho = h2f(*(const uint32_t*)(hin + row*HH + ucol));
                float r0 = sigf(gr.x + acc[mt][tt*3+0][q]   + br.x);
                float r1 = sigf(gr.y + acc[mt][tt*3+0][q+1] + br.y);
                float z0 = sigf(gz.x + acc[mt][tt*3+1][q]   + bz.x);
                float z1 = sigf(gz.y + acc[mt][tt*3+1][q+1] + bz.y);
                float n0v = tanhf(gn.x + r0*(acc[mt][tt*3+2][q]   + bn.x));
                float n1v = tanhf(gn.y + r1*(acc[mt][tt*3+2][q+1] + bn.y));
                float h0 = (1.f - z0)*n0v + z0*ho.x;
                float h1 = (1.f - z1)*n1v + z1*ho.y;
                *(uint32_t*)(hout + row*HH + ucol) = f2h(h0, h1);
                float y0 = fmaf(h0, s2.x, o2.x); y0 = y0>=0.f ? y0 : aA*y0;
                float y1 = fmaf(h1, s2.y, o2.y); y1 = y1>=0.f ? y1 : aA*y1;
                *(uint32_t*)(g_hs16 + (row*LLN + l)*HH + ucol) = f2h(y0, y1);
            }
        }
    }
#undef GISSUE
}

// ---------------- launch ----------------------------------------------------
#define SMEM_BN128 (4*(128*40 + 128*40)*2)   // 81920
#define SMEM_BN32  (4*(128*40 + 32*40)*2)    // 51200

extern "C" void kernel_launch(void* const* d_in, const int* in_sizes, int n_in,
                              void* d_out, int out_size)
{
    const float* A     = (const float*)d_in[0];
    const float* W_lin = (const float*)d_in[1];
    const float* b_lin = (const float*)d_in[2];
    const float* g1    = (const float*)d_in[3];
    const float* be1   = (const float*)d_in[4];
    const float* m1    = (const float*)d_in[5];
    const float* v1    = (const float*)d_in[6];
    const float* a1    = (const float*)d_in[7];
    const float* W_ih  = (const float*)d_in[8];
    const float* W_hh  = (const float*)d_in[9];
    const float* b_ih  = (const float*)d_in[10];
    const float* b_hh  = (const float*)d_in[11];
    const float* g2    = (const float*)d_in[12];
    const float* be2   = (const float*)d_in[13];
    const float* m2    = (const float*)d_in[14];
    const float* v2    = (const float*)d_in[15];
    const float* a2    = (const float*)d_in[16];
    const float* Wc    = (const float*)d_in[17];
    const float* bc    = (const float*)d_in[18];
    const float* g3    = (const float*)d_in[19];
    const float* be3   = (const float*)d_in[20];
    const float* m3    = (const float*)d_in[21];
    const float* v3    = (const float*)d_in[22];
    const float* a3    = (const float*)d_in[23];
    const float* W_mu  = (const float*)d_in[24];
    const float* b_mu  = (const float*)d_in[25];
    float* out = (float*)d_out;

    __half *pxh, *px16, *pgi16, *pha, *phb, *phs16, *py216;
    __half *pwlin, *pwih, *pwc, *pwmu;
    float *pbip;
    cudaGetSymbolAddress((void**)&pxh,   g_xh);
    cudaGetSymbolAddress((void**)&px16,  g_x16);
    cudaGetSymbolAddress((void**)&pgi16, g_gi16);
    cudaGetSymbolAddress((void**)&pha,   g_ha16);
    cudaGetSymbolAddress((void**)&phb,   g_hb16);
    cudaGetSymbolAddress((void**)&phs16, g_hs16);
    cudaGetSymbolAddress((void**)&py216, g_y216);
    cudaGetSymbolAddress((void**)&pwlin, g_wlin16);
    cudaGetSymbolAddress((void**)&pwih,  g_wih16);
    cudaGetSymbolAddress((void**)&pwc,   g_wc16);
    cudaGetSymbolAddress((void**)&pwmu,  g_wmu16);
    cudaGetSymbolAddress((void**)&pbip,  g_bip);

    cudaFuncSetAttribute(hgemm4<128,128,4,2,1,true>, cudaFuncAttributeMaxDynamicSharedMemorySize, SMEM_BN128);
    cudaFuncSetAttribute(hgemm4<128,128,4,2,0,true>, cudaFuncAttributeMaxDynamicSharedMemorySize, SMEM_BN128);
    cudaFuncSetAttribute(hgemm4<128,128,4,2,3,true>, cudaFuncAttributeMaxDynamicSharedMemorySize, SMEM_BN128);
    cudaFuncSetAttribute(hgemm4<128,32,4,2,0,false>, cudaFuncAttributeMaxDynamicSharedMemorySize, SMEM_BN32);
    cudaFuncSetAttribute(gru_gemm, cudaFuncAttributeMaxDynamicSharedMemorySize, GRU_SMEM);

    prep_kernel<<<1, 256>>>(g1, be1, m1, v1, a1, g2, be2, m2, v2, a2, g3, be3, m3, v3, a3,
                            b_ih, b_hh);
    zero_h_kernel<<<(BB*HH/8)/256, 256>>>();

    cvt_kernel<<<(BB*FF/8 + 255)/256, 256>>>(A, pxh, BB*FF/8);
    cvt_w_kernel<<<(CW4 + 255)/256, 256>>>(W_lin, W_ih, W_hh, Wc, W_mu);

    // x = PReLU(BN1(A @ W_lin^T + b_lin)) : [8192,256], K=640
    hgemm4<128,128,4,2,1,true><<<dim3(HH/128, BB/128), 256, SMEM_BN128>>>(pxh, pwlin, b_lin, px16, BB, HH, FF);

    // gi = x @ W_ih_packed^T + b_ih_packed : [8192,768] packed cols, K=256
    hgemm4<128,128,4,2,0,true><<<dim3(GG/128, BB/128), 256, SMEM_BN128>>>(px16, pwih, pbip, pgi16, BB, GG, HH);

    // fused GRU: one GEMM+gate kernel per step, ping-pong h
    __half* hcur = pha;
    __half* hnxt = phb;
    for (int l = 0; l < LLN; l++) {
        gru_gemm<<<dim3(GG/96, BB/128), 256, GRU_SMEM>>>(hcur, hnxt, l);
        __half* tmp = hcur; hcur = hnxt; hnxt = tmp;
    }

    // y2 = PReLU(BN3(hs_bn2 @ Wc^T + bc)) : [163840,256], K=256
    hgemm4<128,128,4,2,3,true><<<dim3(HH/128, BLM/128), 256, SMEM_BN128>>>(phs16, pwc, bc, py216, BLM, HH, HH);

    // pred = y2 @ W_mu^T + b_mu : [163840,32] fp32 out
    hgemm4<128,32,4,2,0,false><<<dim3(1, BLM/128), 256, SMEM_BN32>>>(py216, pwmu, b_mu, out, BLM, CC, HH);
}

// round 17
// speedup vs baseline: 1.4921x; 1.1235x over previous
#include <cuda_runtime.h>
#include <cuda_fp16.h>
#include <math.h>
#include <stdint.h>

#define EE 64
#define SSZ 128
#define FF 640
#define HH 256
#define GG 768          // 3*H
#define LLN 20
#define CC 32
#define BB (EE*SSZ)     // 8192
#define BLM (BB*LLN)    // 163840
#define EPSV 1e-5f

// ---------------- scratch (static __device__, no allocation) ----------------
__device__ __half g_xh [BB*FF];
__device__ __half g_x16[BB*HH];
__device__ __half g_gi16[BB*GG];    // PACKED column order
__device__ __half g_ha16[BB*HH];    // h ping
__device__ __half g_hb16[BB*HH];    // h pong
__device__ __half g_hs16[BLM*HH];   // BN2+PReLU applied
__device__ __half g_y216[BLM*HH];
__device__ __half g_wlin16[HH*FF];
__device__ __half g_wih16[GG*HH];   // PACKED rows
__device__ __half g_whh16[GG*HH];   // PACKED rows
__device__ __half g_wc16[HH*HH];
__device__ __half g_wmu16[CC*HH];
__device__ float g_bip[GG], g_bhp[GG];   // packed biases
__device__ float g_s1[HH], g_o1[HH];
__device__ float g_s2[HH], g_o2[HH];
__device__ float g_s3[HH], g_o3[HH];
__device__ float g_al[3];
__device__ unsigned g_bar;               // grid barrier counter

// ---------------- helpers ----------------------------------------------------
__device__ __forceinline__ uint32_t cvta_s(const void* p) {
    return (uint32_t)__cvta_generic_to_shared(p);
}
__device__ __forceinline__ void mma16(float* c, const uint32_t* a, const uint32_t* b) {
    asm volatile("mma.sync.aligned.m16n8k16.row.col.f32.f16.f16.f32 "
        "{%0,%1,%2,%3},{%4,%5,%6,%7},{%8,%9},{%0,%1,%2,%3};"
        : "+f"(c[0]), "+f"(c[1]), "+f"(c[2]), "+f"(c[3])
        : "r"(a[0]), "r"(a[1]), "r"(a[2]), "r"(a[3]), "r"(b[0]), "r"(b[1]));
}
#define LDSM4(r0,r1,r2,r3,addr) \
    asm volatile("ldmatrix.sync.aligned.m8n8.x4.shared.b16 {%0,%1,%2,%3}, [%4];" \
        : "=r"(r0),"=r"(r1),"=r"(r2),"=r"(r3) : "r"(addr))
#define CP_ASYNC16(dst, src) \
    asm volatile("cp.async.ca.shared.global [%0], [%1], 16;" :: "r"(dst), "l"(src))
#define CP_ASYNC16CG(dst, src) \
    asm volatile("cp.async.cg.shared.global [%0], [%1], 16;" :: "r"(dst), "l"(src))
#define CP_COMMIT() asm volatile("cp.async.commit_group;" ::)
#define CP_WAIT2()  asm volatile("cp.async.wait_group 2;" ::)

__device__ __forceinline__ float sigf(float x) { return 1.f / (1.f + expf(-x)); }
__device__ __forceinline__ float2 h2f(uint32_t u) { return __half22float2(*(__half2*)&u); }
__device__ __forceinline__ uint32_t f2h(float a, float b) {
    __half2 h = __floats2half2_rn(a, b); return *(uint32_t*)&h;
}

// ---------------- prep ------------------------------------------------------
__global__ void prep_kernel(const float* g1,const float* b1,const float* m1,const float* v1,const float* a1,
                            const float* g2,const float* b2,const float* m2,const float* v2,const float* a2,
                            const float* g3,const float* b3,const float* m3,const float* v3,const float* a3,
                            const float* bih, const float* bhh)
{
    int i = threadIdx.x;
    float s;
    s = g1[i] / sqrtf(v1[i] + EPSV); g_s1[i] = s; g_o1[i] = b1[i] - m1[i]*s;
    s = g2[i] / sqrtf(v2[i] + EPSV); g_s2[i] = s; g_o2[i] = b2[i] - m2[i]*s;
    s = g3[i] / sqrtf(v3[i] + EPSV); g_s3[i] = s; g_o3[i] = b3[i] - m3[i]*s;
    if (i == 0) { g_al[0] = a1[0]; g_al[1] = a2[0]; g_al[2] = a3[0]; }
#pragma unroll
    for (int k = 0; k < 3; k++) {
        int p = i + k*256;
        int T = p / 24, rem = p % 24, g = rem >> 3, v = rem & 7;
        int src = g*HH + T*8 + v;
        g_bip[p] = bih[src];
        g_bhp[p] = bhh[src];
    }
}

__global__ void cvt_kernel(const float* __restrict__ s, __half* __restrict__ d, int n8)
{
    int i = blockIdx.x * blockDim.x + threadIdx.x;
    if (i >= n8) return;
    float4 v0 = *(const float4*)(s + i*8);
    float4 v1 = *(const float4*)(s + i*8 + 4);
    *(uint4*)(d + i*8) = make_uint4(f2h(v0.x,v0.y), f2h(v0.z,v0.w), f2h(v1.x,v1.y), f2h(v1.z,v1.w));
}

#define CW0 (HH*FF/8)
#define CW1 (CW0 + GG*HH/8)
#define CW2 (CW1 + GG*HH/8)
#define CW3 (CW2 + HH*HH/8)
#define CW4 (CW3 + CC*HH/8)
__global__ void cvt_w_kernel(const float* wlin, const float* wih, const float* whh,
                             const float* wc, const float* wmu)
{
    int i = blockIdx.x * blockDim.x + threadIdx.x;
    if (i >= CW4) return;
    const float* s; __half* d; size_t sj, dj;
    if (i < CW0)      { s = wlin; d = g_wlin16; sj = dj = (size_t)i; }
    else if (i < CW2) {
        int j = (i < CW1) ? (i - CW0) : (i - CW1);
        s = (i < CW1) ? wih : whh;
        d = (i < CW1) ? g_wih16 : g_whh16;
        int pr = j >> 5, jc = j & 31;
        int T = pr / 24, rem = pr % 24, g = rem >> 3, v = rem & 7;
        sj = (size_t)(g*HH + T*8 + v) * 32 + jc;
        dj = (size_t)j;
    }
    else if (i < CW3) { s = wc;  d = g_wc16;  sj = dj = (size_t)(i - CW2); }
    else              { s = wmu; d = g_wmu16; sj = dj = (size_t)(i - CW3); }
    float4 v0 = *(const float4*)(s + sj*8);
    float4 v1 = *(const float4*)(s + sj*8 + 4);
    *(uint4*)(d + dj*8) = make_uint4(f2h(v0.x,v0.y), f2h(v0.z,v0.w), f2h(v1.x,v1.y), f2h(v1.z,v1.w));
}

__global__ void zero_h_kernel()
{
    int i = blockIdx.x * blockDim.x + threadIdx.x;   // BB*HH/8
    *(uint4*)(g_ha16 + (size_t)i*8) = make_uint4(0,0,0,0);
    if (i == 0) g_bar = 0;
}

// ---------------- fp16 GEMM, 4-stage cp.async (R15, unchanged) ---------------
template<int BM,int BN,int WM,int WN,int MODE,bool OUTH>
__global__ __launch_bounds__(256, 2) void hgemm4(
    const __half* __restrict__ A, const __half* __restrict__ W,
    const float* __restrict__ bias, void* __restrict__ Cst,
    int M, int N, int K)
{
    constexpr int PIT = 40;
    constexpr int ST  = 4;
    extern __shared__ __half smh[];
    __half* Ah = smh;
    __half* Wh = smh + ST*BM*PIT;

    const int tid  = threadIdx.x;
    const int wid  = tid >> 5;
    const int lane = tid & 31;
    const int wm   = wid % WM;
    const int wn   = wid / WM;
    constexpr int WTM = BM / WM;
    constexpr int WTN = BN / WN;
    constexpr int MT  = WTM / 16;
    constexpr int NT  = WTN / 8;
    const int qr = lane >> 2, qc = lane & 3;
    const int l8 = lane & 7;

    const int m0 = blockIdx.y * BM;
    const int n0 = blockIdx.x * BN;

    constexpr int ACH = BM * 4;
    constexpr int WCH = BN * 4;
    constexpr int AIT = ACH / 256;
    constexpr int WIT = (WCH + 255) / 256;

    float acc[MT][NT][4];
#pragma unroll
    for (int i = 0; i < MT; i++)
#pragma unroll
        for (int j = 0; j < NT; j++)
#pragma unroll
            for (int q = 0; q < 4; q++) acc[i][j][q] = 0.f;

    const int T = K / 32;

#define ISSUE_STAGE(st, t) do { \
        _Pragma("unroll") \
        for (int it = 0; it < AIT; it++) { \
            int idx = tid + it*256; int r = idx >> 2, c = idx & 3; \
            uint32_t ds = cvta_s(&Ah[(st)*BM*PIT + r*PIT + c*8]); \
            CP_ASYNC16(ds, A + (size_t)(m0 + r) * K + (size_t)(t)*32 + c*8); \
        } \
        _Pragma("unroll") \
        for (int it = 0; it < WIT; it++) { \
            int idx = tid + it*256; \
            if ((WCH % 256 == 0) || idx < WCH) { \
                int r = idx >> 2, c = idx & 3; \
                uint32_t ds = cvta_s(&Wh[(st)*BN*PIT + r*PIT + c*8]); \
                CP_ASYNC16(ds, W + (size_t)(n0 + r) * K + (size_t)(t)*32 + c*8); \
            } \
        } \
        CP_COMMIT(); \
    } while (0)

    ISSUE_STAGE(0, 0);
    if (T > 1) { ISSUE_STAGE(1, 1); } else { CP_COMMIT(); }
    if (T > 2) { ISSUE_STAGE(2, 2); } else { CP_COMMIT(); }

    for (int t = 0; t < T; t++) {
        CP_WAIT2();
        __syncthreads();
        if (t + 3 < T) { ISSUE_STAGE((t + 3) & 3, t + 3); } else { CP_COMMIT(); }

        const int buf = t & 3;
        const __half* Ab = Ah + buf*BM*PIT;
        const __half* Wb = Wh + buf*BN*PIT;

#pragma unroll
        for (int ks = 0; ks < 2; ks++) {
            uint32_t af[MT][4], bf[NT][2];
#pragma unroll
            for (int mt = 0; mt < MT; mt++) {
                const int m  = wm*WTM + mt*16 + l8 + ((lane >> 3) & 1) * 8;
                const int ck = 2*ks + (lane >> 4);
                uint32_t ad = cvta_s(&Ab[m*PIT + ck*8]);
                LDSM4(af[mt][0], af[mt][1], af[mt][2], af[mt][3], ad);
            }
#pragma unroll
            for (int np = 0; np < NT/2; np++) {
                const int n  = wn*WTN + np*16 + l8 + ((lane >> 4) & 1) * 8;
                const int ck = 2*ks + ((lane >> 3) & 1);
                uint32_t bd = cvta_s(&Wb[n*PIT + ck*8]);
                LDSM4(bf[2*np][0], bf[2*np][1], bf[2*np+1][0], bf[2*np+1][1], bd);
            }
#pragma unroll
            for (int mt = 0; mt < MT; mt++)
#pragma unroll
                for (int nt = 0; nt < NT; nt++)
                    mma16(acc[mt][nt], af[mt], bf[nt]);
        }
    }

#pragma unroll
    for (int mt = 0; mt < MT; mt++) {
#pragma unroll
        for (int nt = 0; nt < NT; nt++) {
            const int row = m0 + wm*WTM + mt*16 + qr;
            const int col = n0 + wn*WTN + nt*8 + 2*qc;
            float2 bv = *(const float2*)(bias + col);
            float x0 = acc[mt][nt][0] + bv.x;
            float x1 = acc[mt][nt][1] + bv.y;
            float x2 = acc[mt][nt][2] + bv.x;
            float x3 = acc[mt][nt][3] + bv.y;
            if (MODE == 1 || MODE == 3) {
                const float* sp = (MODE == 1) ? g_s1 : g_s3;
                const float* op = (MODE == 1) ? g_o1 : g_o3;
                const float al  = (MODE == 1) ? g_al[0] : g_al[2];
                float2 sv = *(const float2*)(sp + col);
                float2 ov = *(const float2*)(op + col);
                x0 = fmaf(x0, sv.x, ov.x); x0 = x0>=0.f ? x0 : al*x0;
                x1 = fmaf(x1, sv.y, ov.y); x1 = x1>=0.f ? x1 : al*x1;
                x2 = fmaf(x2, sv.x, ov.x); x2 = x2>=0.f ? x2 : al*x2;
                x3 = fmaf(x3, sv.y, ov.y); x3 = x3>=0.f ? x3 : al*x3;
            }
            if (OUTH) {
                __half* C = (__half*)Cst;
                *(uint32_t*)&C[(size_t)row * N + col]       = f2h(x0, x1);
                *(uint32_t*)&C[(size_t)(row + 8) * N + col] = f2h(x2, x3);
            } else {
                float* C = (float*)Cst;
                *(float2*)&C[(size_t)row * N + col]       = make_float2(x0, x1);
                *(float2*)&C[(size_t)(row + 8) * N + col] = make_float2(x2, x3);
            }
        }
    }
#undef ISSUE_STAGE
}

// ---------------- persistent fused GRU ---------------------------------------
// 256 CTAs (8 n-blocks x 32 m-pairs), all resident (2/SM). W_hh slab (96x256)
// loaded to smem ONCE; per step each CTA runs 2 M-tiles (A-only 4-stage .cg
// pipeline) + GRU-cell epilogue; device-wide spin barrier between steps.
#define PWR 264                               // resident W pitch (halfs)
#define GRUP_SMEM ((4*128*40 + 96*PWR) * 2)   // 91648 B

__global__ __launch_bounds__(256, 2) void gru_persist2()
{
    constexpr int PIT = 40;
    extern __shared__ __half smh[];
    __half* Ah = smh;                         // [4][128*40]
    __half* Wr = smh + 4*128*PIT;             // [96][PWR]

    const int tid  = threadIdx.x;
    const int wid  = tid >> 5;
    const int lane = tid & 31;
    const int wm   = wid % 4;                 // WTM=32, MT=2
    const int wn   = wid / 4;                 // WTN=48, NT=6
    const int qr = lane >> 2, qc = lane & 3;
    const int l8 = lane & 7;

    const int nb = blockIdx.x & 7;
    const int mb = blockIdx.x >> 3;
    const int n0 = nb * 96;
    const int ub = nb * 32;
    const float aA = g_al[1];

    // ---- load resident W slab: 96 rows x 256 halfs ----
    for (int i = tid; i < 96*32; i += 256) {
        int r = i >> 5, c = i & 31;
        *(uint4*)&Wr[r*PWR + c*8] = *(const uint4*)(g_whh16 + (size_t)(n0 + r) * HH + c*8);
    }
    __syncthreads();

    for (int l = 0; l < LLN; l++) {
        const __half* hin  = (l & 1) ? g_hb16 : g_ha16;
        __half*       hout = (l & 1) ? g_ha16 : g_hb16;

#pragma unroll 1
        for (int mt2 = 0; mt2 < 2; mt2++) {
            const int m0 = (mb*2 + mt2) * 128;

            float acc[2][6][4];
#pragma unroll
            for (int i = 0; i < 2; i++)
#pragma unroll
                for (int j = 0; j < 6; j++)
#pragma unroll
                    for (int q = 0; q < 4; q++) acc[i][j][q] = 0.f;

#define AISSUE(st, t) do { \
        _Pragma("unroll") \
        for (int it = 0; it < 2; it++) { \
            int idx = tid + it*256; int r = idx >> 2, c = idx & 3; \
            uint32_t ds = cvta_s(&Ah[(st)*128*PIT + r*PIT + c*8]); \
            CP_ASYNC16CG(ds, hin + (size_t)(m0 + r) * HH + (size_t)(t)*32 + c*8); \
        } \
        CP_COMMIT(); \
    } while (0)

            AISSUE(0, 0); AISSUE(1, 1); AISSUE(2, 2);

            for (int t = 0; t < 8; t++) {
                CP_WAIT2();
                __syncthreads();
                if (t + 3 < 8) { AISSUE((t + 3) & 3, t + 3); } else { CP_COMMIT(); }

                const int buf = t & 3;
                const __half* Ab = Ah + buf*128*PIT;

#pragma unroll
                for (int ks = 0; ks < 2; ks++) {
                    uint32_t af[2][4], bf[6][2];
#pragma unroll
                    for (int mt = 0; mt < 2; mt++) {
                        const int m  = wm*32 + mt*16 + l8 + ((lane >> 3) & 1) * 8;
                        const int ck = 2*ks + (lane >> 4);
                        uint32_t ad = cvta_s(&Ab[m*PIT + ck*8]);
                        LDSM4(af[mt][0], af[mt][1], af[mt][2], af[mt][3], ad);
                    }
#pragma unroll
                    for (int np = 0; np < 3; np++) {
                        const int n  = wn*48 + np*16 + l8 + ((lane >> 4) & 1) * 8;
                        const int ck = t*4 + 2*ks + ((lane >> 3) & 1);
                        uint32_t bd = cvta_s(&Wr[n*PWR + ck*8]);
                        LDSM4(bf[2*np][0], bf[2*np][1], bf[2*np+1][0], bf[2*np+1][1], bd);
                    }
#pragma unroll
                    for (int mt = 0; mt < 2; mt++)
#pragma unroll
                        for (int nt = 0; nt < 6; nt++)
                            mma16(acc[mt][nt], af[mt], bf[nt]);
                }
            }
#undef AISSUE

            // ---- GRU cell epilogue ----
#pragma unroll
            for (int tt = 0; tt < 2; tt++) {
                const int ucol = ub + (wn*2 + tt)*8 + 2*qc;
                const int cr   = n0 + wn*48 + tt*24 + 2*qc;
                float2 s2 = *(const float2*)(g_s2 + ucol);
                float2 o2 = *(const float2*)(g_o2 + ucol);
                float2 br = *(const float2*)(g_bhp + cr);
                float2 bz = *(const float2*)(g_bhp + cr + 8);
                float2 bn = *(const float2*)(g_bhp + cr + 16);
#pragma unroll
                for (int mt = 0; mt < 2; mt++) {
#pragma unroll
                    for (int hp = 0; hp < 2; hp++) {
                        const size_t row = m0 + wm*32 + mt*16 + qr + hp*8;
                        const int q = hp*2;
                        const __half* gp = g_gi16 + row*GG + cr;
                        float2 gr = h2f(*(const uint32_t*)(gp));
                        float2 gz = h2f(*(const uint32_t*)(gp + 8));
                        float2 gn = h2f(*(const uint32_t*)(gp + 16));
                        float2 ho = h2f(__ldcg((const unsigned int*)(hin + row*HH + ucol)));
                        float r0 = sigf(gr.x + acc[mt][tt*3+0][q]   + br.x);
                        float r1 = sigf(gr.y + acc[mt][tt*3+0][q+1] + br.y);
                        float z0 = sigf(gz.x + acc[mt][tt*3+1][q]   + bz.x);
                        float z1 = sigf(gz.y + acc[mt][tt*3+1][q+1] + bz.y);
                        float n0v = tanhf(gn.x + r0*(acc[mt][tt*3+2][q]   + bn.x));
                        float n1v = tanhf(gn.y + r1*(acc[mt][tt*3+2][q+1] + bn.y));
                        float h0 = (1.f - z0)*n0v + z0*ho.x;
                        float h1 = (1.f - z1)*n1v + z1*ho.y;
                        __stcg((unsigned int*)(hout + row*HH + ucol), f2h(h0, h1));
                        float y0 = fmaf(h0, s2.x, o2.x); y0 = y0>=0.f ? y0 : aA*y0;
                        float y1 = fmaf(h1, s2.y, o2.y); y1 = y1>=0.f ? y1 : aA*y1;
                        *(uint32_t*)(g_hs16 + (row*LLN + l)*HH + ucol) = f2h(y0, y1);
                    }
                }
            }
        }

        // ---- device-wide barrier between steps ----
        if (l + 1 < LLN) {
            __threadfence();
            __syncthreads();
            if (tid == 0) {
                atomicAdd(&g_bar, 1u);
                while (*(volatile unsigned*)&g_bar < 256u * (l + 1)) { }
            }
            __syncthreads();
        }
    }
}

// ---------------- launch ----------------------------------------------------
#define SMEM_BN128 (4*(128*40 + 128*40)*2)   // 81920
#define SMEM_BN32  (4*(128*40 + 32*40)*2)    // 51200

extern "C" void kernel_launch(void* const* d_in, const int* in_sizes, int n_in,
                              void* d_out, int out_size)
{
    const float* A     = (const float*)d_in[0];
    const float* W_lin = (const float*)d_in[1];
    const float* b_lin = (const float*)d_in[2];
    const float* g1    = (const float*)d_in[3];
    const float* be1   = (const float*)d_in[4];
    const float* m1    = (const float*)d_in[5];
    const float* v1    = (const float*)d_in[6];
    const float* a1    = (const float*)d_in[7];
    const float* W_ih  = (const float*)d_in[8];
    const float* W_hh  = (const float*)d_in[9];
    const float* b_ih  = (const float*)d_in[10];
    const float* b_hh  = (const float*)d_in[11];
    const float* g2    = (const float*)d_in[12];
    const float* be2   = (const float*)d_in[13];
    const float* m2    = (const float*)d_in[14];
    const float* v2    = (const float*)d_in[15];
    const float* a2    = (const float*)d_in[16];
    const float* Wc    = (const float*)d_in[17];
    const float* bc    = (const float*)d_in[18];
    const float* g3    = (const float*)d_in[19];
    const float* be3   = (const float*)d_in[20];
    const float* m3    = (const float*)d_in[21];
    const float* v3    = (const float*)d_in[22];
    const float* a3    = (const float*)d_in[23];
    const float* W_mu  = (const float*)d_in[24];
    const float* b_mu  = (const float*)d_in[25];
    float* out = (float*)d_out;

    __half *pxh, *px16, *pgi16, *phs16, *py216;
    __half *pwlin, *pwih, *pwc, *pwmu;
    float *pbip;
    cudaGetSymbolAddress((void**)&pxh,   g_xh);
    cudaGetSymbolAddress((void**)&px16,  g_x16);
    cudaGetSymbolAddress((void**)&pgi16, g_gi16);
    cudaGetSymbolAddress((void**)&phs16, g_hs16);
    cudaGetSymbolAddress((void**)&py216, g_y216);
    cudaGetSymbolAddress((void**)&pwlin, g_wlin16);
    cudaGetSymbolAddress((void**)&pwih,  g_wih16);
    cudaGetSymbolAddress((void**)&pwc,   g_wc16);
    cudaGetSymbolAddress((void**)&pwmu,  g_wmu16);
    cudaGetSymbolAddress((void**)&pbip,  g_bip);

    cudaFuncSetAttribute(hgemm4<128,128,4,2,1,true>, cudaFuncAttributeMaxDynamicSharedMemorySize, SMEM_BN128);
    cudaFuncSetAttribute(hgemm4<128,128,4,2,0,true>, cudaFuncAttributeMaxDynamicSharedMemorySize, SMEM_BN128);
    cudaFuncSetAttribute(hgemm4<128,128,4,2,3,true>, cudaFuncAttributeMaxDynamicSharedMemorySize, SMEM_BN128);
    cudaFuncSetAttribute(hgemm4<128,32,4,2,0,false>, cudaFuncAttributeMaxDynamicSharedMemorySize, SMEM_BN32);
    cudaFuncSetAttribute(gru_persist2, cudaFuncAttributeMaxDynamicSharedMemorySize, GRUP_SMEM);

    prep_kernel<<<1, 256>>>(g1, be1, m1, v1, a1, g2, be2, m2, v2, a2, g3, be3, m3, v3, a3,
                            b_ih, b_hh);
    zero_h_kernel<<<(BB*HH/8)/256, 256>>>();

    cvt_kernel<<<(BB*FF/8 + 255)/256, 256>>>(A, pxh, BB*FF/8);
    cvt_w_kernel<<<(CW4 + 255)/256, 256>>>(W_lin, W_ih, W_hh, Wc, W_mu);

    // x = PReLU(BN1(A @ W_lin^T + b_lin)) : [8192,256], K=640
    hgemm4<128,128,4,2,1,true><<<dim3(HH/128, BB/128), 256, SMEM_BN128>>>(pxh, pwlin, b_lin, px16, BB, HH, FF);

    // gi = x @ W_ih_packed^T + b_ih_packed : [8192,768] packed cols, K=256
    hgemm4<128,128,4,2,0,true><<<dim3(GG/128, BB/128), 256, SMEM_BN128>>>(px16, pwih, pbip, pgi16, BB, GG, HH);

    // persistent fused GRU: all 20 steps, one launch
    gru_persist2<<<256, 256, GRUP_SMEM>>>();

    // y2 = PReLU(BN3(hs_bn2 @ Wc^T + bc)) : [163840,256], K=256
    hgemm4<128,128,4,2,3,true><<<dim3(HH/128, BLM/128), 256, SMEM_BN128>>>(phs16, pwc, bc, py216, BLM, HH, HH);

    // pred = y2 @ W_mu^T + b_mu : [163840,32] fp32 out
    hgemm4<128,32,4,2,0,false><<<dim3(1, BLM/128), 256, SMEM_BN32>>>(py216, pwmu, b_mu, out, BLM, CC, HH);
}